// round 3
// baseline (speedup 1.0000x reference)
#include <cuda_runtime.h>

// Fused grouped-MLP experts kernel, round 1: tf32 mma.sync (m16n8k8), fp32 accum.
// y[b,e,c,l] = b2[e,c] + sum_f W2[e,c,f] * silu( b1[e,f] + sum_c' W1[e,f,c'] * x[b,e,c',l] )
//
// Per CTA: one (expert e, 64-wide column tile of the flattened B*L axis).
//   - X tile [C=256][TN=64] resident in SMEM (tf32-rounded), reused across all F-chunks
//   - loop fc over 16 chunks of TF=64 rows of the hidden dim F=1024:
//       GEMM1: H[64][64] = W1chunk[64][256] @ Xtile   (K=256)
//       bias + silu -> Hs (SMEM, tf32-rounded, stored transposed [n][f])
//       GEMM2: Yacc[256][64] += W2chunk[256][64] @ Hs (K=64)
//   - epilogue: + b2, write fp32
//
// All SMEM strides are ==4 (mod 32) floats so fragment loads are bank-conflict-free.

namespace {

constexpr int E_ = 16, C_ = 256, F_ = 1024, B_ = 8, L_ = 1024;
constexpr int TN = 64;       // columns (b*L) per CTA
constexpr int TF = 64;       // hidden-dim chunk
constexpr int THREADS = 256; // 8 warps

constexpr int XS_STR = C_ + 4;   // 260: Xs[n][c]
constexpr int W1_STR = C_ + 4;   // 260: W1s[f][c]
constexpr int W2_STR = TF + 4;   // 68:  W2s[c][kf]
constexpr int HS_STR = TF + 4;   // 68:  Hs[n][f]

constexpr int XS_FLOATS = TN * XS_STR;   // 16640
constexpr int WS_FLOATS = C_ * W2_STR;   // 17408 (>= TF*W1_STR = 16640; W1/W2 share)
constexpr int HS_FLOATS = TN * HS_STR;   // 4352
constexpr int SMEM_FLOATS = XS_FLOATS + WS_FLOATS + HS_FLOATS;  // 38400
constexpr size_t SMEM_BYTES = (size_t)SMEM_FLOATS * sizeof(float);  // 153600 B

__device__ __forceinline__ float f2tf32(float v) {
    unsigned r;
    asm("cvt.rna.tf32.f32 %0, %1;" : "=r"(r) : "f"(v));
    return __uint_as_float(r);
}

__device__ __forceinline__ void mma_tf32(float* d, const unsigned* a,
                                         unsigned b0, unsigned b1) {
    asm volatile(
        "mma.sync.aligned.m16n8k8.row.col.f32.tf32.tf32.f32 "
        "{%0,%1,%2,%3}, {%4,%5,%6,%7}, {%8,%9}, {%0,%1,%2,%3};\n"
        : "+f"(d[0]), "+f"(d[1]), "+f"(d[2]), "+f"(d[3])
        : "r"(a[0]), "r"(a[1]), "r"(a[2]), "r"(a[3]), "r"(b0), "r"(b1));
}

}  // namespace

__global__ __launch_bounds__(THREADS, 1)
void experts_tf32_kernel(const float* __restrict__ x,
                         const float* __restrict__ W1,
                         const float* __restrict__ b1,
                         const float* __restrict__ W2,
                         const float* __restrict__ b2,
                         float* __restrict__ y) {
    extern __shared__ float smem[];
    float* Xs = smem;                  // [TN][XS_STR]  (transposed: n-major)
    float* Ws = smem + XS_FLOATS;      // W1 chunk [TF][W1_STR] or W2 chunk [C][W2_STR]
    float* Hs = Ws + WS_FLOATS;        // [TN][HS_STR] (transposed: n-major)

    const int tid  = threadIdx.x;
    const int warp = tid >> 5;
    const int lane = tid & 31;
    const int g    = lane >> 2;   // groupID (0..7)
    const int tg   = lane & 3;    // threadID in group (0..3)

    const int e  = blockIdx.y;
    const int n0 = blockIdx.x * TN;        // global column in [0, B*L)
    const int bb = n0 >> 10;               // batch (TN divides L, so tile stays in one b)
    const int l0 = n0 & (L_ - 1);

    const float* xbase = x + (size_t)(bb * E_ * C_ + e * C_) * L_ + l0;
    float*       ybase = y + (size_t)(bb * E_ * C_ + e * C_) * L_ + l0;

    // ---- load X tile (tf32-rounded), Xs[n][c] ----
    #pragma unroll 4
    for (int i = tid; i < C_ * TN; i += THREADS) {
        const int c = i >> 6;
        const int n = i & (TN - 1);
        Xs[n * XS_STR + c] = f2tf32(xbase[(size_t)c * L_ + n]);
    }

    // warp decompositions
    const int warp_hf = warp >> 1;   // GEMM1: 4 f-warps of 16 rows
    const int warp_hn = warp & 1;    // GEMM1: 2 n-warps of 32 cols
    const int warp_yc = warp >> 1;   // GEMM2: 4 c-warps of 64 rows
    const int warp_yn = warp & 1;    // GEMM2: 2 n-warps of 32 cols

    float yacc[4][4][4];
    #pragma unroll
    for (int mi = 0; mi < 4; mi++)
        #pragma unroll
        for (int ni = 0; ni < 4; ni++)
            #pragma unroll
            for (int r = 0; r < 4; r++) yacc[mi][ni][r] = 0.f;

    for (int fc = 0; fc < F_ / TF; fc++) {
        __syncthreads();  // previous GEMM2 done: Ws and Hs free

        // ---- load W1 chunk [TF][C_] (tf32-rounded) ----
        {
            const float* w1p = W1 + (size_t)(e * F_ + fc * TF) * C_;
            #pragma unroll 4
            for (int i = tid; i < TF * C_; i += THREADS) {
                const int fr = i >> 8;
                const int c  = i & (C_ - 1);
                Ws[fr * W1_STR + c] = f2tf32(w1p[fr * C_ + c]);
            }
        }
        __syncthreads();

        // ---- GEMM1: H[TF][TN] = W1chunk @ Xtile, K = 256 ----
        float hacc[4][4];
        #pragma unroll
        for (int ni = 0; ni < 4; ni++)
            #pragma unroll
            for (int r = 0; r < 4; r++) hacc[ni][r] = 0.f;

        const int fb  = warp_hf * 16;
        const int n1b = warp_hn * 32;
        #pragma unroll
        for (int k0 = 0; k0 < C_; k0 += 8) {
            unsigned a[4];
            a[0] = __float_as_uint(Ws[(fb + g)     * W1_STR + k0 + tg]);
            a[1] = __float_as_uint(Ws[(fb + g + 8) * W1_STR + k0 + tg]);
            a[2] = __float_as_uint(Ws[(fb + g)     * W1_STR + k0 + tg + 4]);
            a[3] = __float_as_uint(Ws[(fb + g + 8) * W1_STR + k0 + tg + 4]);
            #pragma unroll
            for (int ni = 0; ni < 4; ni++) {
                const int nb = n1b + ni * 8;
                const unsigned b0v = __float_as_uint(Xs[(nb + g) * XS_STR + k0 + tg]);
                const unsigned b1v = __float_as_uint(Xs[(nb + g) * XS_STR + k0 + tg + 4]);
                mma_tf32(hacc[ni], a, b0v, b1v);
            }
        }

        // ---- bias + silu, store Hs[n][f] (tf32-rounded) ----
        {
            const float* b1p = b1 + e * F_ + fc * TF;
            #pragma unroll
            for (int ni = 0; ni < 4; ni++) {
                #pragma unroll
                for (int r = 0; r < 4; r++) {
                    const int fl = fb + g + ((r >> 1) << 3);
                    const int nn = n1b + ni * 8 + tg * 2 + (r & 1);
                    float v = hacc[ni][r] + b1p[fl];
                    v = v / (1.f + __expf(-v));  // silu; saturates correctly at +/-inf
                    Hs[nn * HS_STR + fl] = f2tf32(v);
                }
            }
        }
        __syncthreads();  // GEMM1 reads of Ws + all Hs writes done

        // ---- load W2 chunk [C_][TF] (tf32-rounded) ----
        {
            const float* w2p = W2 + (size_t)(e * C_) * F_ + fc * TF;
            #pragma unroll 4
            for (int i = tid; i < C_ * TF; i += THREADS) {
                const int c  = i >> 6;
                const int kf = i & (TF - 1);
                Ws[c * W2_STR + kf] = f2tf32(w2p[(size_t)c * F_ + kf]);
            }
        }
        __syncthreads();

        // ---- GEMM2: Yacc[C_][TN] += W2chunk @ Hs, K = TF ----
        #pragma unroll
        for (int k0 = 0; k0 < TF; k0 += 8) {
            unsigned a[4][4];
            #pragma unroll
            for (int mi = 0; mi < 4; mi++) {
                const int cb = warp_yc * 64 + mi * 16;
                a[mi][0] = __float_as_uint(Ws[(cb + g)     * W2_STR + k0 + tg]);
                a[mi][1] = __float_as_uint(Ws[(cb + g + 8) * W2_STR + k0 + tg]);
                a[mi][2] = __float_as_uint(Ws[(cb + g)     * W2_STR + k0 + tg + 4]);
                a[mi][3] = __float_as_uint(Ws[(cb + g + 8) * W2_STR + k0 + tg + 4]);
            }
            #pragma unroll
            for (int ni = 0; ni < 4; ni++) {
                const int nb = warp_yn * 32 + ni * 8;
                const unsigned b0v = __float_as_uint(Hs[(nb + g) * HS_STR + k0 + tg]);
                const unsigned b1v = __float_as_uint(Hs[(nb + g) * HS_STR + k0 + tg + 4]);
                #pragma unroll
                for (int mi = 0; mi < 4; mi++)
                    mma_tf32(yacc[mi][ni], a[mi], b0v, b1v);
            }
        }
    }

    // ---- epilogue: + b2, write y ----
    #pragma unroll
    for (int mi = 0; mi < 4; mi++) {
        #pragma unroll
        for (int r2 = 0; r2 < 2; r2++) {
            const int cl = warp_yc * 64 + mi * 16 + g + r2 * 8;
            const float bias = b2[e * C_ + cl];
            #pragma unroll
            for (int ni = 0; ni < 4; ni++) {
                const int nn = warp_yn * 32 + ni * 8 + tg * 2;
                float2 v;
                v.x = yacc[mi][ni][r2 * 2 + 0] + bias;
                v.y = yacc[mi][ni][r2 * 2 + 1] + bias;
                *reinterpret_cast<float2*>(&ybase[(size_t)cl * L_ + nn]) = v;
            }
        }
    }
}

extern "C" void kernel_launch(void* const* d_in, const int* in_sizes, int n_in,
                              void* d_out, int out_size) {
    const float* x  = (const float*)d_in[0];
    const float* W1 = (const float*)d_in[1];
    const float* b1 = (const float*)d_in[2];
    const float* W2 = (const float*)d_in[3];
    const float* b2 = (const float*)d_in[4];
    float* y = (float*)d_out;

    cudaFuncSetAttribute(experts_tf32_kernel,
                         cudaFuncAttributeMaxDynamicSharedMemorySize,
                         (int)SMEM_BYTES);

    dim3 grid((B_ * L_) / TN, E_);   // 128 x 16 = 2048 CTAs
    experts_tf32_kernel<<<grid, THREADS, SMEM_BYTES>>>(x, W1, b1, W2, b2, y);
}

// round 6
// speedup vs baseline: 3.4705x; 3.4705x over previous
#include <cuda_runtime.h>
#include <cstdint>

// Round 4: two-stage unfused tf32 mma.sync GEMMs (sm_103 target has NO tcgen05).
//   K1: Ht[p][l][f] = tf32( silu( W1_e @ X_p + b1 ) )   CTA tile M=128(f) N=128(l) K=256
//   K2: y[p][c][l]  = W2_e @ Ht + b2                    CTA tile M=128(c) N=128(l) K=1024
// cp.async 3-stage pipeline, 1 syncthreads per K-chunk, 2 CTAs/SM, smem-staged
// coalesced epilogues. Operands rounded to tf32 (cvt.rna) at fragment-load time.

namespace {

constexpr int E_ = 16, C_ = 256, F_ = 1024, L_ = 1024, B_ = 8;

__device__ float g_Ht[(size_t)B_ * E_ * L_ * F_];  // 512 MB scratch: Ht[p][l][f]

__device__ __forceinline__ unsigned tf32b(float v) {
    unsigned r; asm("cvt.rna.tf32.f32 %0, %1;" : "=r"(r) : "f"(v)); return r;
}
__device__ __forceinline__ float f2tf32(float v) { return __uint_as_float(tf32b(v)); }

__device__ __forceinline__ void mma_tf32(float* d, const unsigned* a,
                                         unsigned b0, unsigned b1) {
    asm volatile(
        "mma.sync.aligned.m16n8k8.row.col.f32.tf32.tf32.f32 "
        "{%0,%1,%2,%3}, {%4,%5,%6,%7}, {%8,%9}, {%0,%1,%2,%3};\n"
        : "+f"(d[0]), "+f"(d[1]), "+f"(d[2]), "+f"(d[3])
        : "r"(a[0]), "r"(a[1]), "r"(a[2]), "r"(a[3]), "r"(b0), "r"(b1));
}
__device__ __forceinline__ uint32_t smem_u32(const void* p) {
    uint32_t a;
    asm("{ .reg .u64 t; cvta.to.shared.u64 t, %1; cvt.u32.u64 %0, t; }" : "=r"(a) : "l"(p));
    return a;
}
__device__ __forceinline__ void cp16(uint32_t dst, const void* src) {
    asm volatile("cp.async.cg.shared.global [%0], [%1], 16;\n" :: "r"(dst), "l"(src));
}
__device__ __forceinline__ void cp_commit() { asm volatile("cp.async.commit_group;\n"); }
template <int N> __device__ __forceinline__ void cp_wait() {
    asm volatile("cp.async.wait_group %0;\n" :: "n"(N));
}

// smem strides (floats). All == 4 or 8 (mod 32) -> conflict-free fragment LDS.
constexpr int A_STR  = 36;   // [row][k] tiles, k-chunk 32
constexpr int B1_STR = 132;  // K1 B: X chunk [k=32][l=128]
constexpr int B2_STR = 36;   // K2 B: Ht chunk [l=128][k=32]
constexpr int ST1_STR = 132; // K1 staging [l=128][f=128]
constexpr int ST2_STR = 136; // K2 staging [c=128][l=128] (8 mod 32: float2 conflict-free)

constexpr int K1_ABUF = 128 * A_STR;   // 4608 fl
constexpr int K1_BBUF = 32 * B1_STR;   // 4224 fl
constexpr int K2_ABUF = 128 * A_STR;   // 4608 fl
constexpr int K2_BBUF = 128 * B2_STR;  // 4608 fl

constexpr size_t K1_SMEM = (size_t)(3 * K1_ABUF + 3 * K1_BBUF) * 4;  // 105984 B
constexpr size_t K2_SMEM = (size_t)(3 * K2_ABUF + 3 * K2_BBUF) * 4;  // 110592 B
// staging (16896 / 17408 fl) reuses the pipeline buffers after the mainloop.

}  // namespace

// ===================== K1: Ht = tf32(silu(W1 @ X + b1)) =====================
__global__ __launch_bounds__(256, 2)
void experts_k1(const float* __restrict__ x, const float* __restrict__ W1,
                const float* __restrict__ b1) {
    extern __shared__ float sm[];
    float* As = sm;                    // 3 x [128 f][36]
    float* Bs = sm + 3 * K1_ABUF;      // 3 x [32 k][132]
    const uint32_t As_u = smem_u32(As), Bs_u = smem_u32(Bs);

    const int tid = threadIdx.x, warp = tid >> 5, lane = tid & 31;
    const int g = lane >> 2, tg = lane & 3;
    const int p = blockIdx.z, e = p & (E_ - 1);
    const int fbase = blockIdx.y * 128, l0 = blockIdx.x * 128;

    const float* W1p = W1 + (size_t)(e * F_ + fbase) * C_;
    const float* xp  = x + (size_t)p * C_ * L_ + l0;

    const int warpM = warp >> 1, warpN = warp & 1;  // 4 x 2 warp grid
    const int fb0 = warpM * 32, nb0 = warpN * 64;   // warp tile 32(f) x 64(l)

    auto load_chunk = [&](int kc, int buf) {
        const float* wsrc = W1p + kc * 32;
        const uint32_t ad = As_u + (uint32_t)(buf * K1_ABUF) * 4;
        #pragma unroll
        for (int it = 0; it < 4; it++) {            // A: 128 rows x 8 float4
            const int idx = tid + it * 256;
            const int f = idx >> 3, k4 = (idx & 7) * 4;
            cp16(ad + (uint32_t)(f * A_STR + k4) * 4, wsrc + (size_t)f * C_ + k4);
        }
        const float* xsrc = xp + (size_t)(kc * 32) * L_;
        const uint32_t bd = Bs_u + (uint32_t)(buf * K1_BBUF) * 4;
        #pragma unroll
        for (int it = 0; it < 4; it++) {            // B: 32 rows x 32 float4
            const int idx = tid + it * 256;
            const int c = idx >> 5, l4 = (idx & 31) * 4;
            cp16(bd + (uint32_t)(c * B1_STR + l4) * 4, xsrc + (size_t)c * L_ + l4);
        }
    };

    float acc[2][8][4];
    #pragma unroll
    for (int mi = 0; mi < 2; mi++)
        #pragma unroll
        for (int ni = 0; ni < 8; ni++)
            #pragma unroll
            for (int r = 0; r < 4; r++) acc[mi][ni][r] = 0.f;

    load_chunk(0, 0); cp_commit();
    load_chunk(1, 1); cp_commit();

    for (int kc = 0; kc < 8; kc++) {
        cp_wait<1>();
        __syncthreads();
        if (kc + 2 < 8) load_chunk(kc + 2, (kc + 2) % 3);
        cp_commit();  // empty groups keep wait_group counting uniform

        const float* Ab = As + (kc % 3) * K1_ABUF;
        const float* Bb = Bs + (kc % 3) * K1_BBUF;
        #pragma unroll
        for (int k0 = 0; k0 < 32; k0 += 8) {
            unsigned a[2][4];
            #pragma unroll
            for (int mi = 0; mi < 2; mi++) {
                const float* ap = Ab + (fb0 + mi * 16 + g) * A_STR + k0 + tg;
                a[mi][0] = tf32b(ap[0]);
                a[mi][1] = tf32b(ap[8 * A_STR]);
                a[mi][2] = tf32b(ap[4]);
                a[mi][3] = tf32b(ap[8 * A_STR + 4]);
            }
            #pragma unroll
            for (int ni = 0; ni < 8; ni++) {
                const float* bp = Bb + (k0 + tg) * B1_STR + nb0 + ni * 8 + g;
                const unsigned b0 = tf32b(bp[0]);
                const unsigned b1v = tf32b(bp[4 * B1_STR]);
                mma_tf32(acc[0][ni], a[0], b0, b1v);
                mma_tf32(acc[1][ni], a[1], b0, b1v);
            }
        }
    }
    __syncthreads();  // pipeline buffers free -> staging

    float bias[2][2];
    #pragma unroll
    for (int mi = 0; mi < 2; mi++)
        #pragma unroll
        for (int h = 0; h < 2; h++)
            bias[mi][h] = __ldg(b1 + e * F_ + fbase + fb0 + mi * 16 + g + h * 8);

    float* stg = sm;  // [l=128][ST1_STR]
    #pragma unroll
    for (int mi = 0; mi < 2; mi++)
        #pragma unroll
        for (int ni = 0; ni < 8; ni++)
            #pragma unroll
            for (int r = 0; r < 4; r++) {
                const int f = fb0 + mi * 16 + g + (r >> 1) * 8;
                const int l = nb0 + ni * 8 + tg * 2 + (r & 1);
                float v = acc[mi][ni][r] + bias[mi][r >> 1];
                v = v / (1.f + __expf(-v));         // silu
                stg[l * ST1_STR + f] = f2tf32(v);
            }
    __syncthreads();

    float* Hp = g_Ht + ((size_t)p * L_ + l0) * F_ + fbase;
    #pragma unroll
    for (int it = 0; it < 16; it++) {
        const int i4 = tid + it * 256;
        const int row = i4 >> 5, fo = (i4 & 31) * 4;
        const float4 v = *(const float4*)(stg + row * ST1_STR + fo);
        *(float4*)(Hp + (size_t)row * F_ + fo) = v;
    }
}

// ===================== K2: y = W2 @ Ht + b2 =====================
__global__ __launch_bounds__(256, 2)
void experts_k2(const float* __restrict__ W2, const float* __restrict__ b2,
                float* __restrict__ y) {
    extern __shared__ float sm[];
    float* As = sm;                    // 3 x [128 c][36]
    float* Bs = sm + 3 * K2_ABUF;      // 3 x [128 l][36]
    const uint32_t As_u = smem_u32(As), Bs_u = smem_u32(Bs);

    const int tid = threadIdx.x, warp = tid >> 5, lane = tid & 31;
    const int g = lane >> 2, tg = lane & 3;
    const int p = blockIdx.z, e = p & (E_ - 1);
    const int cbase = blockIdx.y * 128, l0 = blockIdx.x * 128;

    const float* W2p = W2 + (size_t)(e * C_ + cbase) * F_;
    const float* Hb  = g_Ht + ((size_t)p * L_ + l0) * F_;

    const int warpM = warp >> 1, warpN = warp & 1;
    const int cb0 = warpM * 32, nb0 = warpN * 64;

    auto load_chunk = [&](int kc, int buf) {
        const float* wsrc = W2p + kc * 32;
        const uint32_t ad = As_u + (uint32_t)(buf * K2_ABUF) * 4;
        #pragma unroll
        for (int it = 0; it < 4; it++) {            // A: 128 c rows x 8 float4
            const int idx = tid + it * 256;
            const int c = idx >> 3, k4 = (idx & 7) * 4;
            cp16(ad + (uint32_t)(c * A_STR + k4) * 4, wsrc + (size_t)c * F_ + k4);
        }
        const float* hsrc = Hb + kc * 32;
        const uint32_t bd = Bs_u + (uint32_t)(buf * K2_BBUF) * 4;
        #pragma unroll
        for (int it = 0; it < 4; it++) {            // B: 128 l rows x 8 float4
            const int idx = tid + it * 256;
            const int l = idx >> 3, k4 = (idx & 7) * 4;
            cp16(bd + (uint32_t)(l * B2_STR + k4) * 4, hsrc + (size_t)l * F_ + k4);
        }
    };

    float acc[2][8][4];
    #pragma unroll
    for (int mi = 0; mi < 2; mi++)
        #pragma unroll
        for (int ni = 0; ni < 8; ni++)
            #pragma unroll
            for (int r = 0; r < 4; r++) acc[mi][ni][r] = 0.f;

    load_chunk(0, 0); cp_commit();
    load_chunk(1, 1); cp_commit();

    for (int kc = 0; kc < 32; kc++) {
        cp_wait<1>();
        __syncthreads();
        if (kc + 2 < 32) load_chunk(kc + 2, (kc + 2) % 3);
        cp_commit();

        const float* Ab = As + (kc % 3) * K2_ABUF;
        const float* Bb = Bs + (kc % 3) * K2_BBUF;
        #pragma unroll
        for (int k0 = 0; k0 < 32; k0 += 8) {
            unsigned a[2][4];
            #pragma unroll
            for (int mi = 0; mi < 2; mi++) {
                const float* ap = Ab + (cb0 + mi * 16 + g) * A_STR + k0 + tg;
                a[mi][0] = tf32b(ap[0]);
                a[mi][1] = tf32b(ap[8 * A_STR]);
                a[mi][2] = tf32b(ap[4]);
                a[mi][3] = tf32b(ap[8 * A_STR + 4]);
            }
            #pragma unroll
            for (int ni = 0; ni < 8; ni++) {
                // Ht already tf32-rounded: raw bit loads, no cvt
                const float* bp = Bb + (nb0 + ni * 8 + g) * B2_STR + k0 + tg;
                const unsigned b0  = __float_as_uint(bp[0]);
                const unsigned b1v = __float_as_uint(bp[4]);
                mma_tf32(acc[0][ni], a[0], b0, b1v);
                mma_tf32(acc[1][ni], a[1], b0, b1v);
            }
        }
    }
    __syncthreads();  // pipeline buffers free -> staging

    float bias[2][2];
    #pragma unroll
    for (int mi = 0; mi < 2; mi++)
        #pragma unroll
        for (int h = 0; h < 2; h++)
            bias[mi][h] = __ldg(b2 + e * C_ + cbase + cb0 + mi * 16 + g + h * 8);

    float* stg = sm;  // [c=128][ST2_STR]
    #pragma unroll
    for (int mi = 0; mi < 2; mi++)
        #pragma unroll
        for (int ni = 0; ni < 8; ni++)
            #pragma unroll
            for (int r2 = 0; r2 < 2; r2++) {
                const int c = cb0 + mi * 16 + g + r2 * 8;
                const int l = nb0 + ni * 8 + tg * 2;
                float2 v;
                v.x = acc[mi][ni][r2 * 2 + 0] + bias[mi][r2];
                v.y = acc[mi][ni][r2 * 2 + 1] + bias[mi][r2];
                *(float2*)(stg + c * ST2_STR + l) = v;
            }
    __syncthreads();

    float* yp = y + ((size_t)p * C_ + cbase) * L_ + l0;
    #pragma unroll
    for (int it = 0; it < 16; it++) {
        const int i4 = tid + it * 256;
        const int c = i4 >> 5, lo = (i4 & 31) * 4;
        const float4 v = *(const float4*)(stg + c * ST2_STR + lo);
        *(float4*)(yp + (size_t)c * L_ + lo) = v;
    }
}

extern "C" void kernel_launch(void* const* d_in, const int* in_sizes, int n_in,
                              void* d_out, int out_size) {
    const float* x  = (const float*)d_in[0];
    const float* W1 = (const float*)d_in[1];
    const float* b1 = (const float*)d_in[2];
    const float* W2 = (const float*)d_in[3];
    const float* b2 = (const float*)d_in[4];
    float* y = (float*)d_out;

    cudaFuncSetAttribute(experts_k1, cudaFuncAttributeMaxDynamicSharedMemorySize, (int)K1_SMEM);
    cudaFuncSetAttribute(experts_k2, cudaFuncAttributeMaxDynamicSharedMemorySize, (int)K2_SMEM);

    experts_k1<<<dim3(L_ / 128, F_ / 128, B_ * E_), 256, K1_SMEM>>>(x, W1, b1);   // 8192 CTAs
    experts_k2<<<dim3(L_ / 128, C_ / 128, B_ * E_), 256, K2_SMEM>>>(W2, b2, y);   // 2048 CTAs
}

// round 11
// speedup vs baseline: 4.0736x; 1.1738x over previous
#include <cuda_runtime.h>
#include <cstdint>

// Round 6: packed-fragment tf32 HMMA GEMMs.
//   prep: round W1/W2/x to tf32 and repack into mma.m16n8k8 fragment order.
//   K1: Htf = packedB( silu(W1 @ X + b1) )    CTA 128(f) x 128(l), K=256
//   K2: y   = W2 @ Ht + b2                    CTA 128(c) x 128(l), K=1024
// Mainloop fragment loads are single LDS.128 (A) / LDS.64 (B), zero cvt.
// cp.async 3-stage pipeline (linear 16KB chunk copies), 2 CTAs/SM.
//
// Packed layouts (per K-chunk kc of 32, g=lane>>2, tg=lane&3):
//   A[k0][m8][lane][4] : (A[m8*16+g][k0*8+tg], A[..+8+g][tg], A[g][tg+4], A[+8+g][tg+4])
//   B[k0][nb][lane][2] : (B[nb*8+g][k0*8+tg], B[nb*8+g][k0*8+tg+4])      (B[n][k])

namespace {

constexpr int E_ = 16, C_ = 256, F_ = 1024, L_ = 1024, B_ = 8;
constexpr int CHUNK = 4096;  // floats per packed 32-K chunk (16 KB)

__device__ float g_W1f[(size_t)E_ * F_ * C_];        //   16 MB
__device__ float g_W2f[(size_t)E_ * C_ * F_];        //   16 MB
__device__ float g_Xf [(size_t)B_ * E_ * C_ * L_];   //  128 MB
__device__ float g_Htf[(size_t)B_ * E_ * L_ * F_];   //  512 MB

__device__ __forceinline__ unsigned tf32b(float v) {
    unsigned r; asm("cvt.rna.tf32.f32 %0, %1;" : "=r"(r) : "f"(v)); return r;
}
__device__ __forceinline__ float f2tf32(float v) { return __uint_as_float(tf32b(v)); }

__device__ __forceinline__ void mma_tf32(float* d, const unsigned* a,
                                         unsigned b0, unsigned b1) {
    asm volatile(
        "mma.sync.aligned.m16n8k8.row.col.f32.tf32.tf32.f32 "
        "{%0,%1,%2,%3}, {%4,%5,%6,%7}, {%8,%9}, {%0,%1,%2,%3};\n"
        : "+f"(d[0]), "+f"(d[1]), "+f"(d[2]), "+f"(d[3])
        : "r"(a[0]), "r"(a[1]), "r"(a[2]), "r"(a[3]), "r"(b0), "r"(b1));
}
__device__ __forceinline__ uint32_t smem_u32(const void* p) {
    uint32_t a;
    asm("{ .reg .u64 t; cvta.to.shared.u64 t, %1; cvt.u32.u64 %0, t; }" : "=r"(a) : "l"(p));
    return a;
}
__device__ __forceinline__ void cp16(uint32_t dst, const void* src) {
    asm volatile("cp.async.cg.shared.global [%0], [%1], 16;\n" :: "r"(dst), "l"(src));
}
__device__ __forceinline__ void cp_commit() { asm volatile("cp.async.commit_group;\n"); }
template <int N> __device__ __forceinline__ void cp_wait() {
    asm volatile("cp.async.wait_group %0;\n" :: "n"(N));
}

constexpr size_t MAIN_SMEM = (size_t)(3 * 2 * CHUNK) * 4;  // 98304 B (3 stages x A+B)
constexpr int ST1_STR = 132;  // K1 staging [l][f]
constexpr int ST2_STR = 136;  // K2 staging [c][l]

}  // namespace

// ===================== prep kernels =====================
// W1 -> g_W1f[e][ft(8)][kc(8)][CHUNK]; A-matrix rows f (128/tile), k = c
__global__ __launch_bounds__(256, 4)
void prep_w1(const float* __restrict__ W1) {
    __shared__ float ws[128][36];
    const int e = blockIdx.y, ft = blockIdx.x, tid = threadIdx.x;
    const float* src = W1 + (size_t)(e * F_ + ft * 128) * C_;
    float* dst = g_W1f + ((size_t)(e * 8 + ft) * 8) * CHUNK;
    for (int kc = 0; kc < 8; kc++) {
        __syncthreads();
        #pragma unroll
        for (int it = 0; it < 4; it++) {  // 128 rows x 8 float4
            const int idx = tid + it * 256, f = idx >> 3, c4 = (idx & 7) * 4;
            const float4 v = *(const float4*)(src + (size_t)f * C_ + kc * 32 + c4);
            ws[f][c4] = f2tf32(v.x); ws[f][c4 + 1] = f2tf32(v.y);
            ws[f][c4 + 2] = f2tf32(v.z); ws[f][c4 + 3] = f2tf32(v.w);
        }
        __syncthreads();
        #pragma unroll
        for (int it = 0; it < 4; it++) {  // 1024 float4 packed
            const int i4 = tid + it * 256;
            const int k0 = i4 >> 8, m8 = (i4 >> 5) & 7, lane = i4 & 31;
            const int g = lane >> 2, tg = lane & 3;
            float4 v;
            v.x = ws[m8 * 16 + g][k0 * 8 + tg];
            v.y = ws[m8 * 16 + 8 + g][k0 * 8 + tg];
            v.z = ws[m8 * 16 + g][k0 * 8 + tg + 4];
            v.w = ws[m8 * 16 + 8 + g][k0 * 8 + tg + 4];
            *(float4*)(dst + (size_t)kc * CHUNK + i4 * 4) = v;
        }
    }
}

// W2 -> g_W2f[e][cb(2)][kc(32)][CHUNK]; A-matrix rows c (128/tile), k = f
__global__ __launch_bounds__(256, 4)
void prep_w2(const float* __restrict__ W2) {
    __shared__ float ws[128][36];
    const int e = blockIdx.y, cb = blockIdx.x, tid = threadIdx.x;
    const float* src = W2 + (size_t)(e * C_ + cb * 128) * F_;
    float* dst = g_W2f + ((size_t)(e * 2 + cb) * 32) * CHUNK;
    for (int kc = 0; kc < 32; kc++) {
        __syncthreads();
        #pragma unroll
        for (int it = 0; it < 4; it++) {
            const int idx = tid + it * 256, c = idx >> 3, f4 = (idx & 7) * 4;
            const float4 v = *(const float4*)(src + (size_t)c * F_ + kc * 32 + f4);
            ws[c][f4] = f2tf32(v.x); ws[c][f4 + 1] = f2tf32(v.y);
            ws[c][f4 + 2] = f2tf32(v.z); ws[c][f4 + 3] = f2tf32(v.w);
        }
        __syncthreads();
        #pragma unroll
        for (int it = 0; it < 4; it++) {
            const int i4 = tid + it * 256;
            const int k0 = i4 >> 8, m8 = (i4 >> 5) & 7, lane = i4 & 31;
            const int g = lane >> 2, tg = lane & 3;
            float4 v;
            v.x = ws[m8 * 16 + g][k0 * 8 + tg];
            v.y = ws[m8 * 16 + 8 + g][k0 * 8 + tg];
            v.z = ws[m8 * 16 + g][k0 * 8 + tg + 4];
            v.w = ws[m8 * 16 + 8 + g][k0 * 8 + tg + 4];
            *(float4*)(dst + (size_t)kc * CHUNK + i4 * 4) = v;
        }
    }
}

// x -> g_Xf[p][lt(8)][kc(8)][CHUNK]; B-matrix n = l (128/tile), k = c
__global__ __launch_bounds__(256, 4)
void prep_x(const float* __restrict__ x) {
    __shared__ float xs[32][136];
    const int p = blockIdx.y, lt = blockIdx.x, tid = threadIdx.x;
    const float* src = x + (size_t)p * C_ * L_ + lt * 128;
    float* dst = g_Xf + ((size_t)(p * 8 + lt) * 8) * CHUNK;
    for (int kc = 0; kc < 8; kc++) {
        __syncthreads();
        #pragma unroll
        for (int it = 0; it < 4; it++) {  // 32 rows x 32 float4
            const int idx = tid + it * 256, c = idx >> 5, l4 = (idx & 31) * 4;
            const float4 v = *(const float4*)(src + (size_t)(kc * 32 + c) * L_ + l4);
            xs[c][l4] = f2tf32(v.x); xs[c][l4 + 1] = f2tf32(v.y);
            xs[c][l4 + 2] = f2tf32(v.z); xs[c][l4 + 3] = f2tf32(v.w);
        }
        __syncthreads();
        #pragma unroll
        for (int it = 0; it < 8; it++) {  // 2048 float2 packed
            const int i2 = tid + it * 256;
            const int k0 = i2 >> 9, nb = (i2 >> 5) & 15, lane = i2 & 31;
            const int g = lane >> 2, tg = lane & 3;
            float2 v;
            v.x = xs[k0 * 8 + tg][nb * 8 + g];
            v.y = xs[k0 * 8 + tg + 4][nb * 8 + g];
            *(float2*)(dst + (size_t)kc * CHUNK + i2 * 2) = v;
        }
    }
}

// ===================== K1: Htf = packedB(silu(W1 @ X + b1)) =====================
__global__ __launch_bounds__(256, 2)
void experts_k1(const float* __restrict__ b1) {
    extern __shared__ float sm[];
    const uint32_t sm_u = smem_u32(sm);

    const int tid = threadIdx.x, warp = tid >> 5, lane = tid & 31;
    const int g = lane >> 2, tg = lane & 3;
    const int p = blockIdx.z, e = p & (E_ - 1);
    const int ft = blockIdx.y, lt = blockIdx.x;

    const float* Aglob = g_W1f + ((size_t)(e * 8 + ft) * 8) * CHUNK;
    const float* Bglob = g_Xf + ((size_t)(p * 8 + lt) * 8) * CHUNK;

    const int warpM = warp >> 1, warpN = warp & 1;  // 4x2: warp tile 32(f) x 64(l)

    auto load_chunk = [&](int kc, int buf) {
        const uint32_t ad = sm_u + (uint32_t)(buf * 2 * CHUNK) * 4;
        const float* as = Aglob + (size_t)kc * CHUNK;
        const float* bs = Bglob + (size_t)kc * CHUNK;
        #pragma unroll
        for (int it = 0; it < 4; it++) {
            const int i4 = tid + it * 256;
            cp16(ad + (uint32_t)i4 * 16, as + i4 * 4);
            cp16(ad + (uint32_t)(CHUNK + i4 * 4) * 4, bs + i4 * 4);
        }
    };

    float acc[2][8][4];
    #pragma unroll
    for (int mi = 0; mi < 2; mi++)
        #pragma unroll
        for (int ni = 0; ni < 8; ni++)
            #pragma unroll
            for (int r = 0; r < 4; r++) acc[mi][ni][r] = 0.f;

    load_chunk(0, 0); cp_commit();
    load_chunk(1, 1); cp_commit();

    for (int kc = 0; kc < 8; kc++) {
        cp_wait<1>();
        __syncthreads();
        if (kc + 2 < 8) load_chunk(kc + 2, (kc + 2) % 3);
        cp_commit();

        const float* Ab = sm + (kc % 3) * 2 * CHUNK;
        const float* Bb = Ab + CHUNK;
        #pragma unroll
        for (int k0 = 0; k0 < 4; k0++) {
            unsigned a[2][4];
            #pragma unroll
            for (int mi = 0; mi < 2; mi++) {
                const int m8 = warpM * 2 + mi;
                const float4 v = *(const float4*)(Ab + ((k0 * 8 + m8) * 32 + lane) * 4);
                a[mi][0] = __float_as_uint(v.x); a[mi][1] = __float_as_uint(v.y);
                a[mi][2] = __float_as_uint(v.z); a[mi][3] = __float_as_uint(v.w);
            }
            #pragma unroll
            for (int ni = 0; ni < 8; ni++) {
                const int nb = warpN * 8 + ni;
                const float2 b = *(const float2*)(Bb + ((k0 * 16 + nb) * 32 + lane) * 2);
                const unsigned b0 = __float_as_uint(b.x), b1v = __float_as_uint(b.y);
                mma_tf32(acc[0][ni], a[0], b0, b1v);
                mma_tf32(acc[1][ni], a[1], b0, b1v);
            }
        }
    }
    cp_wait<0>();
    __syncthreads();  // pipeline buffers free -> staging

    float bias[2][2];
    #pragma unroll
    for (int mi = 0; mi < 2; mi++)
        #pragma unroll
        for (int hi = 0; hi < 2; hi++)
            bias[mi][hi] = __ldg(b1 + e * F_ + ft * 128 + (warpM * 2 + mi) * 16 + g + hi * 8);

    float* stg = sm;  // [l=128][ST1_STR]  (67.6 KB)
    #pragma unroll
    for (int mi = 0; mi < 2; mi++)
        #pragma unroll
        for (int ni = 0; ni < 8; ni++)
            #pragma unroll
            for (int r = 0; r < 4; r++) {
                const int fL = (warpM * 2 + mi) * 16 + g + (r >> 1) * 8;
                const int l = warpN * 64 + ni * 8 + tg * 2 + (r & 1);
                float v = acc[mi][ni][r] + bias[mi][r >> 1];
                v = v / (1.f + __expf(-v));  // silu
                stg[l * ST1_STR + fL] = f2tf32(v);
            }
    __syncthreads();

    // write Ht in K2's packed-B layout: [p][lt][kc(32)][k0][nb][lane][2]
    float* dst = g_Htf + (((size_t)(p * 8 + lt) * 32 + ft * 4)) * CHUNK;
    #pragma unroll
    for (int it = 0; it < 32; it++) {
        const int i2 = tid + it * 256;             // [0, 8192)
        const int kcL = i2 >> 11, rem = i2 & 2047;
        const int k0 = rem >> 9, nb = (rem >> 5) & 15, ln = rem & 31;
        const int gg = ln >> 2, tt = ln & 3;
        const int l = nb * 8 + gg;
        const int fL = kcL * 32 + k0 * 8 + tt;
        float2 v;
        v.x = stg[l * ST1_STR + fL];
        v.y = stg[l * ST1_STR + fL + 4];
        *(float2*)(dst + (size_t)kcL * CHUNK + rem * 2) = v;
    }
}

// ===================== K2: y = W2 @ Ht + b2 =====================
__global__ __launch_bounds__(256, 2)
void experts_k2(const float* __restrict__ b2, float* __restrict__ y) {
    extern __shared__ float sm[];
    const uint32_t sm_u = smem_u32(sm);

    const int tid = threadIdx.x, warp = tid >> 5, lane = tid & 31;
    const int g = lane >> 2, tg = lane & 3;
    const int p = blockIdx.z, e = p & (E_ - 1);
    const int cb = blockIdx.y, lt = blockIdx.x;

    const float* Aglob = g_W2f + ((size_t)(e * 2 + cb) * 32) * CHUNK;
    const float* Bglob = g_Htf + ((size_t)(p * 8 + lt) * 32) * CHUNK;

    const int warpM = warp >> 1, warpN = warp & 1;

    auto load_chunk = [&](int kc, int buf) {
        const uint32_t ad = sm_u + (uint32_t)(buf * 2 * CHUNK) * 4;
        const float* as = Aglob + (size_t)kc * CHUNK;
        const float* bs = Bglob + (size_t)kc * CHUNK;
        #pragma unroll
        for (int it = 0; it < 4; it++) {
            const int i4 = tid + it * 256;
            cp16(ad + (uint32_t)i4 * 16, as + i4 * 4);
            cp16(ad + (uint32_t)(CHUNK + i4 * 4) * 4, bs + i4 * 4);
        }
    };

    float acc[2][8][4];
    #pragma unroll
    for (int mi = 0; mi < 2; mi++)
        #pragma unroll
        for (int ni = 0; ni < 8; ni++)
            #pragma unroll
            for (int r = 0; r < 4; r++) acc[mi][ni][r] = 0.f;

    load_chunk(0, 0); cp_commit();
    load_chunk(1, 1); cp_commit();

    for (int kc = 0; kc < 32; kc++) {
        cp_wait<1>();
        __syncthreads();
        if (kc + 2 < 32) load_chunk(kc + 2, (kc + 2) % 3);
        cp_commit();

        const float* Ab = sm + (kc % 3) * 2 * CHUNK;
        const float* Bb = Ab + CHUNK;
        #pragma unroll
        for (int k0 = 0; k0 < 4; k0++) {
            unsigned a[2][4];
            #pragma unroll
            for (int mi = 0; mi < 2; mi++) {
                const int m8 = warpM * 2 + mi;
                const float4 v = *(const float4*)(Ab + ((k0 * 8 + m8) * 32 + lane) * 4);
                a[mi][0] = __float_as_uint(v.x); a[mi][1] = __float_as_uint(v.y);
                a[mi][2] = __float_as_uint(v.z); a[mi][3] = __float_as_uint(v.w);
            }
            #pragma unroll
            for (int ni = 0; ni < 8; ni++) {
                const int nb = warpN * 8 + ni;
                const float2 b = *(const float2*)(Bb + ((k0 * 16 + nb) * 32 + lane) * 2);
                const unsigned b0 = __float_as_uint(b.x), b1v = __float_as_uint(b.y);
                mma_tf32(acc[0][ni], a[0], b0, b1v);
                mma_tf32(acc[1][ni], a[1], b0, b1v);
            }
        }
    }
    cp_wait<0>();
    __syncthreads();  // pipeline buffers free -> staging

    float bias[2][2];
    #pragma unroll
    for (int mi = 0; mi < 2; mi++)
        #pragma unroll
        for (int hi = 0; hi < 2; hi++)
            bias[mi][hi] = __ldg(b2 + e * C_ + cb * 128 + (warpM * 2 + mi) * 16 + g + hi * 8);

    float* stg = sm;  // [c=128][ST2_STR]  (69.6 KB)
    #pragma unroll
    for (int mi = 0; mi < 2; mi++)
        #pragma unroll
        for (int ni = 0; ni < 8; ni++)
            #pragma unroll
            for (int r2 = 0; r2 < 2; r2++) {
                const int c = (warpM * 2 + mi) * 16 + g + r2 * 8;
                const int l = warpN * 64 + ni * 8 + tg * 2;
                float2 v;
                v.x = acc[mi][ni][r2 * 2 + 0] + bias[mi][r2];
                v.y = acc[mi][ni][r2 * 2 + 1] + bias[mi][r2];
                *(float2*)(stg + c * ST2_STR + l) = v;
            }
    __syncthreads();

    float* yp = y + ((size_t)p * C_ + cb * 128) * L_ + lt * 128;
    #pragma unroll
    for (int it = 0; it < 16; it++) {
        const int i4 = tid + it * 256;
        const int c = i4 >> 5, lo = (i4 & 31) * 4;
        const float4 v = *(const float4*)(stg + c * ST2_STR + lo);
        *(float4*)(yp + (size_t)c * L_ + lo) = v;
    }
}

extern "C" void kernel_launch(void* const* d_in, const int* in_sizes, int n_in,
                              void* d_out, int out_size) {
    const float* x  = (const float*)d_in[0];
    const float* W1 = (const float*)d_in[1];
    const float* b1 = (const float*)d_in[2];
    const float* W2 = (const float*)d_in[3];
    const float* b2 = (const float*)d_in[4];
    float* y = (float*)d_out;

    cudaFuncSetAttribute(experts_k1, cudaFuncAttributeMaxDynamicSharedMemorySize, (int)MAIN_SMEM);
    cudaFuncSetAttribute(experts_k2, cudaFuncAttributeMaxDynamicSharedMemorySize, (int)MAIN_SMEM);

    prep_x <<<dim3(8, B_ * E_), 256>>>(x);     // 1024 CTAs
    prep_w1<<<dim3(8, E_), 256>>>(W1);         //  128 CTAs
    prep_w2<<<dim3(2, E_), 256>>>(W2);         //   32 CTAs

    experts_k1<<<dim3(8, 8, B_ * E_), 256, MAIN_SMEM>>>(b1);        // 8192 CTAs
    experts_k2<<<dim3(8, 2, B_ * E_), 256, MAIN_SMEM>>>(b2, y);     // 2048 CTAs
}